// round 1
// baseline (speedup 1.0000x reference)
#include <cuda_runtime.h>
#include <cuda_bf16.h>
#include <cstddef>

// GATNE-T fused inference kernel.
// Inputs (metadata order):
//  0 targets   int32  [B]
//  1 types     int32  [B]
//  2 neighbors int32  [B,T,S]
//  3 base_node_embeddings float [V,E]
//  4 node_type_embeddings float [V,T,D]
//  5 trans_weights    float [T,D,E]
//  6 trans_weights_s1 float [T,D,A]
//  7 trans_weights_s2 float [T,A,1]
// Output: float [B,E]
//
// B=8192, T=4, S=10, D=32, E=128, A=32, V=500000.
// One CTA per batch element, 128 threads = 4 warps (warp t = edge type t,
// lane = embedding dim). Gathers are fully coalesced 128B segments.

namespace {
constexpr int T = 4;
constexpr int S = 10;
constexpr int D = 32;
constexpr int E = 128;
constexpr int A = 32;
}

__global__ __launch_bounds__(128) void gatne_t_kernel(
    const int* __restrict__ targets,
    const int* __restrict__ types,
    const int* __restrict__ neighbors,
    const float* __restrict__ base_emb,   // [V,E]
    const float* __restrict__ nte,        // [V,T,D]
    const float* __restrict__ tw,         // [T,D,E]
    const float* __restrict__ tw1,        // [T,D,A]
    const float* __restrict__ tw2,        // [T,A]
    float* __restrict__ out)              // [B,E]
{
    const int b    = blockIdx.x;
    const int tid  = threadIdx.x;     // 0..127
    const int warp = tid >> 5;        // edge type t
    const int lane = tid & 31;        // dim d (or attention dim a)

    __shared__ float sh_agg[T][D];    // node_agg[b]
    __shared__ float sh_sc[T];        // attention scores
    __shared__ float sh_natt[D];      // attended node embedding
    __shared__ float sh_red[T];       // l2-norm partial sums

    const int type = types[b];

    // ---- neighbor gather + mean (the DRAM-bound part) ----
    // warp t, lane d accumulates sum_s nte[nb[s]][t][d].
    const int* nb = neighbors + (size_t)b * (T * S) + warp * S;
    int vidx[S];
    #pragma unroll
    for (int s = 0; s < S; ++s) vidx[s] = nb[s];

    float acc = 0.0f;
    #pragma unroll
    for (int s = 0; s < S; ++s) {
        // independent loads -> MLP = 10 per warp
        acc += __ldg(&nte[(size_t)vidx[s] * (T * D) + warp * D + lane]);
    }
    acc *= (1.0f / (float)S);
    sh_agg[warp][lane] = acc;
    __syncthreads();

    // ---- u = tanh(node_agg @ tw1[type]); score = u @ tw2[type] ----
    // warp t, lane a
    const float* w1 = tw1 + (size_t)type * (D * A);
    float dot = 0.0f;
    #pragma unroll
    for (int d = 0; d < D; ++d)
        dot = fmaf(sh_agg[warp][d], w1[d * A + lane], dot);
    float sc = tanhf(dot) * tw2[type * A + lane];
    #pragma unroll
    for (int off = 16; off > 0; off >>= 1)
        sc += __shfl_xor_sync(0xffffffffu, sc, off);
    if (lane == 0) sh_sc[warp] = sc;
    __syncthreads();

    // ---- softmax over T=4 (computed redundantly, cheap) ----
    const float s0 = sh_sc[0], s1 = sh_sc[1], s2 = sh_sc[2], s3 = sh_sc[3];
    const float m  = fmaxf(fmaxf(s0, s1), fmaxf(s2, s3));
    const float e0 = __expf(s0 - m), e1 = __expf(s1 - m);
    const float e2 = __expf(s2 - m), e3 = __expf(s3 - m);
    const float inv = 1.0f / (e0 + e1 + e2 + e3);

    // ---- node_att[d] = sum_t att[t] * node_agg[t][d] ----
    if (warp == 0) {
        float natt = e0 * sh_agg[0][lane] + e1 * sh_agg[1][lane]
                   + e2 * sh_agg[2][lane] + e3 * sh_agg[3][lane];
        sh_natt[lane] = natt * inv;
    }
    __syncthreads();

    // ---- proj[e] = node_att @ tw[type]  (thread tid = output dim e) ----
    const float* w = tw + (size_t)type * (D * E);
    float p = 0.0f;
    #pragma unroll
    for (int d = 0; d < D; ++d)
        p = fmaf(sh_natt[d], w[d * E + tid], p);

    const int tgt = targets[b];
    const float val = __ldg(&base_emb[(size_t)tgt * E + tid]) + p;

    // ---- l2 normalize over the 128 output dims ----
    float sq = val * val;
    #pragma unroll
    for (int off = 16; off > 0; off >>= 1)
        sq += __shfl_xor_sync(0xffffffffu, sq, off);
    if (lane == 0) sh_red[warp] = sq;
    __syncthreads();
    const float tot = sh_red[0] + sh_red[1] + sh_red[2] + sh_red[3];
    const float r = rsqrtf(fmaxf(tot, 1e-12f));

    out[(size_t)b * E + tid] = val * r;
}

extern "C" void kernel_launch(void* const* d_in, const int* in_sizes, int n_in,
                              void* d_out, int out_size) {
    const int*   targets   = (const int*)  d_in[0];
    const int*   types     = (const int*)  d_in[1];
    const int*   neighbors = (const int*)  d_in[2];
    const float* base_emb  = (const float*)d_in[3];
    const float* nte       = (const float*)d_in[4];
    const float* tw        = (const float*)d_in[5];
    const float* tw1       = (const float*)d_in[6];
    const float* tw2       = (const float*)d_in[7];
    float* out = (float*)d_out;

    const int B = in_sizes[0];  // 8192
    gatne_t_kernel<<<B, 128>>>(targets, types, neighbors,
                               base_emb, nte, tw, tw1, tw2, out);
}